// round 7
// baseline (speedup 1.0000x reference)
#include <cuda_runtime.h>
#include <math.h>

#define BS 512
#define NN 256
#define MAXITER 200
#define OMEGA 1.5f
#define RB4 20          // float4 chunks in registers (cols 0..79)
#define SB4 44          // float4 chunks in smem     (cols 80..255)

// smem float offsets
#define EBUF  0                       // 256 (single live e buffer)
#define WRED  256                     // 16 (2 banks x 8)
#define WRED2 272                     // 8
#define RS    288                     // 32 (+pad to 320)
#define MAT   320                     // SB4*NN*4 = 45056 floats
#define SCR   (MAT + SB4*NN*4)        // 8 * 1056
#define SMEM_FLOATS (SCR + 8*1056)    // 53824 floats = 215296 B

// consume newly-published 64-col block B into acc (acc -= C[:,B]·e[B])
template<int B>
__device__ __forceinline__ void consume_blk(float& acc, const float4* __restrict__ creg,
        const float4* __restrict__ sT4, const float4* __restrict__ eb4, int tid)
{
    float a0 = 0.f, a1 = 0.f, a2 = 0.f, a3 = 0.f;
#pragma unroll
    for (int k = 0; k < 16; ++k) {
        const int ch = 16 * B + k;
        float4 c;
        if (ch < RB4) c = creg[ch]; else c = sT4[(ch - RB4) * NN + tid];
        const float4 e = eb4[ch];
        a0 = fmaf(c.x, e.x, a0); a1 = fmaf(c.y, e.y, a1);
        a2 = fmaf(c.z, e.z, a2); a3 = fmaf(c.w, e.w, a3);
    }
    acc -= (a0 + a1) + (a2 + a3);
}

// dense 64x64 unit-lower solve for group P: e_new = Minv * acc; publish; reinit acc
template<int P>
__device__ __forceinline__ void solve_blk(float& acc, float& en, float& normv,
        const float* __restrict__ Mrow, const float* __restrict__ scr,
        float* __restrict__ r_s, float* __restrict__ ebuf, int wid, int lane, int tid)
{
    const float r = acc;
    if ((wid & 1) == 0) r_s[lane] = r;
    asm volatile("bar.sync %0, %1;" :: "r"(P + 1), "r"(64) : "memory");
    float e0a = 0.f, e1a = 0.f, e2a = 0.f, e3a = 0.f;
    if ((wid & 1) == 0) {
#pragma unroll
        for (int k = 0; k < 32; k += 4) {
            e0a = fmaf(Mrow[k+0], __shfl_sync(0xffffffffu, r, k+0), e0a);
            e1a = fmaf(Mrow[k+1], __shfl_sync(0xffffffffu, r, k+1), e1a);
            e2a = fmaf(Mrow[k+2], __shfl_sync(0xffffffffu, r, k+2), e2a);
            e3a = fmaf(Mrow[k+3], __shfl_sync(0xffffffffu, r, k+3), e3a);
        }
    } else {
        const float* Bl = scr + (wid - 1) * 1056 + lane * 33;
#pragma unroll
        for (int k = 0; k < 32; k += 2) {
            e0a = fmaf(Bl[k+0], r_s[k+0], e0a);
            e1a = fmaf(Mrow[k+0], __shfl_sync(0xffffffffu, r, k+0), e1a);
            e2a = fmaf(Bl[k+1], r_s[k+1], e2a);
            e3a = fmaf(Mrow[k+1], __shfl_sync(0xffffffffu, r, k+1), e3a);
        }
    }
    en = (e0a + e1a) + (e2a + e3a);
    ebuf[tid] = en;                    // publish own row
    acc = (1.0f - OMEGA) * en;         // start accumulator for next iteration
    normv = en * en;                   // norm partial (reduced later, off-path)
}

__device__ __forceinline__ void norm_pub(float normv, float* __restrict__ wred,
                                         int bank, int wid, int lane)
{
    float v = normv;
#pragma unroll
    for (int o = 16; o; o >>= 1) v += __shfl_xor_sync(0xffffffffu, v, o);
    if (lane == 0) wred[bank * 8 + wid] = v;
}

__global__ void __launch_bounds__(NN, 1) sor_fused(
    const float* __restrict__ A, const float* __restrict__ xs,
    const float* __restrict__ theta, const float* __restrict__ rtol,
    float* __restrict__ out)
{
    extern __shared__ float sm[];
    float*  ebuf = sm + EBUF;
    float*  wred = sm + WRED;
    float*  wred2= sm + WRED2;
    float*  r_s  = sm + RS;
    float4* sT4  = (float4*)(sm + MAT);
    float*  sTf  = sm + MAT;
    float*  scr  = sm + SCR;
    const float4* eb4 = (const float4*)ebuf;

    const int b = blockIdx.x, tid = threadIdx.x;
    const int wid = tid >> 5, lane = tid & 31, g = wid >> 1;
    const size_t obase = (size_t)b * (MAXITER + 1);

    // ---------------- load row `tid` of A, scale by omega / a_ii ----------------
    const float*  Ar  = A + ((size_t)b * NN + tid) * NN;
    const float4* Ar4 = (const float4*)Ar;
    const float sc = OMEGA / Ar[tid];
    float4 creg[RB4];
#pragma unroll
    for (int jb = 0; jb < RB4; ++jb) {
        float4 v = Ar4[jb];
        v.x *= sc; v.y *= sc; v.z *= sc; v.w *= sc;
        creg[jb] = v;
    }
#pragma unroll 4
    for (int jb = 0; jb < SB4; ++jb) {
        float4 v = Ar4[RB4 + jb];
        v.x *= sc; v.y *= sc; v.z *= sc; v.w *= sc;
        sT4[jb * NN + tid] = v;
    }

    // ---------------- e0 = xs - theta; partial norms ----------------------------
    const float xv = xs[b * NN + tid];
    const float e0v = xv - theta[b * NN + tid];
    ebuf[tid] = e0v;
    {
        float s1 = e0v * e0v, s2 = xv * xv;
#pragma unroll
        for (int o = 16; o; o >>= 1) {
            s1 += __shfl_xor_sync(0xffffffffu, s1, o);
            s2 += __shfl_xor_sync(0xffffffffu, s2, o);
        }
        if (lane == 0) { wred[wid] = s1; wred2[wid] = s2; }
    }

    // ---------------- per-warp 32x32 unit-lower diag block -> scratch -----------
    float* myscr = scr + wid * 1056;
    if (wid == 0) {
#pragma unroll
        for (int k = 0; k < 8; ++k) {
            const float4 v = creg[k];
            myscr[lane*33+4*k+0]=v.x; myscr[lane*33+4*k+1]=v.y;
            myscr[lane*33+4*k+2]=v.z; myscr[lane*33+4*k+3]=v.w;
        }
    } else if (wid == 1) {
#pragma unroll
        for (int k = 0; k < 8; ++k) {
            const float4 v = creg[8 + k];
            myscr[lane*33+4*k+0]=v.x; myscr[lane*33+4*k+1]=v.y;
            myscr[lane*33+4*k+2]=v.z; myscr[lane*33+4*k+3]=v.w;
        }
    } else if (wid == 2) {
#pragma unroll
        for (int k = 0; k < 4; ++k) {
            const float4 v = creg[16 + k];
            myscr[lane*33+4*k+0]=v.x; myscr[lane*33+4*k+1]=v.y;
            myscr[lane*33+4*k+2]=v.z; myscr[lane*33+4*k+3]=v.w;
        }
#pragma unroll
        for (int k = 4; k < 8; ++k) {
            const float4 v = sT4[(k - 4) * NN + tid];
            myscr[lane*33+4*k+0]=v.x; myscr[lane*33+4*k+1]=v.y;
            myscr[lane*33+4*k+2]=v.z; myscr[lane*33+4*k+3]=v.w;
        }
    } else {
        const int jb0 = wid * 8 - RB4;
#pragma unroll
        for (int k = 0; k < 8; ++k) {
            const float4 v = sT4[(jb0 + k) * NN + tid];
            myscr[lane*33+4*k+0]=v.x; myscr[lane*33+4*k+1]=v.y;
            myscr[lane*33+4*k+2]=v.z; myscr[lane*33+4*k+3]=v.w;
        }
    }
    __syncwarp();
    {   // invert unit-lower 32x32: lane c builds column c
        float mcol[32];
#pragma unroll
        for (int r = 0; r < 32; ++r) mcol[r] = (r == lane) ? 1.f : 0.f;
#pragma unroll
        for (int r = 1; r < 32; ++r) {
            float s = 0.f;
#pragma unroll
            for (int j = 0; j < r; ++j) s = fmaf(myscr[r * 33 + j], mcol[j], s);
            mcol[r] -= s;
        }
        __syncwarp();
#pragma unroll
        for (int r = 0; r < 32; ++r) myscr[r * 33 + lane] = mcol[r];
    }
    __syncwarp();
    float Mrow[32];
#pragma unroll
    for (int c = 0; c < 32; ++c) Mrow[c] = myscr[lane * 33 + c];

    __syncthreads();   // wred/wred2 ready; partner scratch (M11) ready

    // ---------------- err0 / xtol (identical in every thread) -------------------
    float errp, xtol;
    {
        float a1 = 0.f, a2 = 0.f;
#pragma unroll
        for (int w = 0; w < 8; ++w) { a1 += wred[w]; a2 += wred2[w]; }
        errp = sqrtf(a1);
        xtol = sqrtf(a2) * rtol[b];
        if (tid == 0) out[obase] = errp;
    }

    // ---------------- odd warps: B = -M22 * (C21 * M11) -> overwrite M11 slot ---
    if (wid & 1) {
        float* escr = scr + (wid - 1) * 1056;
        float* oscr = myscr;
        float c21[32];
        if (wid == 1) {
#pragma unroll
            for (int k = 0; k < 8; ++k) {
                const float4 v = creg[k];
                c21[4*k+0]=v.x; c21[4*k+1]=v.y; c21[4*k+2]=v.z; c21[4*k+3]=v.w;
            }
        } else if (wid == 3) {
#pragma unroll
            for (int k = 0; k < 4; ++k) {
                const float4 v = creg[16 + k];
                c21[4*k+0]=v.x; c21[4*k+1]=v.y; c21[4*k+2]=v.z; c21[4*k+3]=v.w;
            }
#pragma unroll
            for (int k = 4; k < 8; ++k) {
                const float4 v = sT4[(k - 4) * NN + tid];
                c21[4*k+0]=v.x; c21[4*k+1]=v.y; c21[4*k+2]=v.z; c21[4*k+3]=v.w;
            }
        } else if (wid == 5) {
#pragma unroll
            for (int k = 0; k < 8; ++k) {
                const float4 v = sT4[(12 + k) * NN + tid];
                c21[4*k+0]=v.x; c21[4*k+1]=v.y; c21[4*k+2]=v.z; c21[4*k+3]=v.w;
            }
        } else {
#pragma unroll
            for (int k = 0; k < 8; ++k) {
                const float4 v = sT4[(28 + k) * NN + tid];
                c21[4*k+0]=v.x; c21[4*k+1]=v.y; c21[4*k+2]=v.z; c21[4*k+3]=v.w;
            }
        }
#pragma unroll 1
        for (int c = 0; c < 32; ++c) {   // X = C21 * M11
            float x = 0.f;
#pragma unroll
            for (int j = 0; j < 32; ++j) x = fmaf(c21[j], escr[j * 33 + c], x);
            oscr[lane * 33 + c] = x;
        }
        __syncwarp();
#pragma unroll 1
        for (int c = 0; c < 32; ++c) {   // B = -M22 * X, overwrite M11
            float y = 0.f;
#pragma unroll
            for (int j = 0; j < 32; ++j) y = fmaf(Mrow[j], oscr[j * 33 + c], y);
            escr[lane * 33 + c] = -y;
        }
    }

    // ---------------- zero own-64-block entries j <= tid ------------------------
    if (g == 0) {
#pragma unroll
        for (int s = 0; s < 64; ++s) if (s <= tid) {
            float4& v = creg[s >> 2];
            if ((s & 3) == 0) v.x = 0.f; else if ((s & 3) == 1) v.y = 0.f;
            else if ((s & 3) == 2) v.z = 0.f; else v.w = 0.f;
        }
    } else if (g == 1) {
#pragma unroll
        for (int s = 0; s < 16; ++s) { const int j = 64 + s; if (j <= tid) {
            float4& v = creg[16 + (s >> 2)];
            if ((s & 3) == 0) v.x = 0.f; else if ((s & 3) == 1) v.y = 0.f;
            else if ((s & 3) == 2) v.z = 0.f; else v.w = 0.f;
        } }
#pragma unroll
        for (int s = 16; s < 64; ++s) { const int j = 64 + s; if (j <= tid)
            sTf[((((s - 16) >> 2)) * NN + tid) * 4 + (s & 3)] = 0.f; }
    } else if (g == 2) {
#pragma unroll
        for (int s = 0; s < 64; ++s) { const int j = 128 + s; if (j <= tid)
            sTf[((12 + (s >> 2)) * NN + tid) * 4 + (s & 3)] = 0.f; }
    } else {
#pragma unroll
        for (int s = 0; s < 64; ++s) { const int j = 192 + s; if (j <= tid)
            sTf[((28 + (s >> 2)) * NN + tid) * 4 + (s & 3)] = 0.f; }
    }
    __syncthreads();   // B, e0, zeroed matrix visible

    // ---------------- prologue: acc for iter 1 from e0 (blocks >= g) ------------
    float acc = (1.0f - OMEGA) * e0v;
    if (g == 0) {
        consume_blk<0>(acc, creg, sT4, eb4, tid);
        consume_blk<1>(acc, creg, sT4, eb4, tid);
        consume_blk<2>(acc, creg, sT4, eb4, tid);
        consume_blk<3>(acc, creg, sT4, eb4, tid);
    } else if (g == 1) {
        consume_blk<1>(acc, creg, sT4, eb4, tid);
        consume_blk<2>(acc, creg, sT4, eb4, tid);
        consume_blk<3>(acc, creg, sT4, eb4, tid);
    } else if (g == 2) {
        consume_blk<2>(acc, creg, sT4, eb4, tid);
        consume_blk<3>(acc, creg, sT4, eb4, tid);
    } else {
        consume_blk<3>(acc, creg, sT4, eb4, tid);
    }

    // ---------------- pipelined mainloop ----------------------------------------
    float en = 0.f, normv = 0.f;
    int t = 1;
    for (; t <= MAXITER; ++t) {
        // ======== stage 0 ========
        __syncthreads();                       // block 3 of iter t-1 published
        if (t > 1) {
            float s = 0.f;
#pragma unroll
            for (int w = 0; w < 8; ++w) s += wred[(((t - 1) & 1)) * 8 + w];
            errp = sqrtf(s);
            if (tid == 0) out[obase + (t - 1)] = errp;
        }
        if (errp <= xtol) break;
        if (t > 1) consume_blk<3>(acc, creg, sT4, eb4, tid);
        if (g == 0) solve_blk<0>(acc, en, normv, Mrow, scr, r_s, ebuf, wid, lane, tid);

        // ======== stage 1 ========
        __syncthreads();                       // block 0 of iter t published
        consume_blk<0>(acc, creg, sT4, eb4, tid);
        if (g == 0) norm_pub(normv, wred, t & 1, wid, lane);          // deferred
        if (g == 1) solve_blk<1>(acc, en, normv, Mrow, scr, r_s, ebuf, wid, lane, tid);

        // ======== stage 2 ========
        __syncthreads();                       // block 1 published
        consume_blk<1>(acc, creg, sT4, eb4, tid);
        if (g == 1) norm_pub(normv, wred, t & 1, wid, lane);          // deferred
        if (g == 2) solve_blk<2>(acc, en, normv, Mrow, scr, r_s, ebuf, wid, lane, tid);

        // ======== stage 3 ========
        __syncthreads();                       // block 2 published
        consume_blk<2>(acc, creg, sT4, eb4, tid);
        if (g == 2) norm_pub(normv, wred, t & 1, wid, lane);          // deferred
        if (g == 3) {
            solve_blk<3>(acc, en, normv, Mrow, scr, r_s, ebuf, wid, lane, tid);
            norm_pub(normv, wred, t & 1, wid, lane);                  // inline (last)
        }
    }

    // ---------------- epilogue ---------------------------------------------------
    int zf;
    if (t > MAXITER) {     // natural exit: err_MAXITER still unwritten
        __syncthreads();
        float s = 0.f;
#pragma unroll
        for (int w = 0; w < 8; ++w) s += wred[((MAXITER & 1)) * 8 + w];
        if (tid == 0) out[obase + MAXITER] = sqrtf(s);
        zf = MAXITER + 1;
    } else {
        zf = t;            // broke at pass t: out[t-1] written, zero t..MAXITER
    }
    for (int z = zf + tid; z <= MAXITER; z += NN)
        out[obase + z] = 0.f;
}

// ---------------------------------------------------------------------------
extern "C" void kernel_launch(void* const* d_in, const int* in_sizes, int n_in,
                              void* d_out, int out_size) {
    const float* A     = (const float*)d_in[0];
    // d_in[1] = b — not needed (error-vector formulation)
    const float* xs    = (const float*)d_in[2];
    const float* theta = (const float*)d_in[3];
    const float* rtol  = (const float*)d_in[4];
    float* out = (float*)d_out;

    static int smem_set = 0;
    if (!smem_set) {
        cudaFuncSetAttribute(sor_fused, cudaFuncAttributeMaxDynamicSharedMemorySize,
                             SMEM_FLOATS * (int)sizeof(float));
        smem_set = 1;
    }
    sor_fused<<<BS, NN, SMEM_FLOATS * sizeof(float)>>>(A, xs, theta, rtol, out);
}

// round 8
// speedup vs baseline: 1.6559x; 1.6559x over previous
#include <cuda_runtime.h>
#include <cuda_fp16.h>
#include <math.h>

#define BS 512
#define NN 256
#define MAXITER 200
#define OMEGA 1.5f

// smem float offsets
#define SM_EH    0                        // 256 half = 128 floats (scaled e-hat)
#define SM_WRED  128                      // [2][8]
#define SM_WRED2 144                      // [8]
#define SM_MAT   160                      // 16 uint4-chunks x 256 rows = 16384 floats
#define SM_SCR   (SM_MAT + 16 * NN * 4)   // 8 * 1056 floats (fp32 inverse scratch)
#define SMEM_FLOATS (SM_SCR + 8 * 1056)   // 24992 floats = 99968 B (x2 CTAs/SM)

__device__ __forceinline__ __half2 u2h(unsigned int u) { return *(__half2*)&u; }
__device__ __forceinline__ unsigned int h2u(__half2 h) { return *(unsigned int*)&h; }

// dot of 8 cols: c,e are 4 packed half2 each; half chain then fp32 upconvert
__device__ __forceinline__ float dot8h(uint4 c, uint4 e) {
    __half2 h = __hmul2(u2h(c.x), u2h(e.x));
    h = __hfma2(u2h(c.y), u2h(e.y), h);
    h = __hfma2(u2h(c.z), u2h(e.z), h);
    h = __hfma2(u2h(c.w), u2h(e.w), h);
    const float2 f = __half22float2(h);
    return f.x + f.y;
}

// consume 32-col block Q (chunks 4Q..4Q+3): acc -= sp * C[:,Q]·ehat[Q]
template<int Q>
__device__ __forceinline__ void consume32(float& acc, float sp,
        const uint4* cregs, const uint4* __restrict__ sH4,
        const uint4* __restrict__ eh4, int tid)
{
    float d0, d1, d2, d3;
    {
        const int ch = 4 * Q + 0;
        const uint4 c = (ch < 16) ? cregs[ch] : sH4[(ch - 16) * NN + tid];
        d0 = dot8h(c, eh4[ch]);
    }
    {
        const int ch = 4 * Q + 1;
        const uint4 c = (ch < 16) ? cregs[ch] : sH4[(ch - 16) * NN + tid];
        d1 = dot8h(c, eh4[ch]);
    }
    {
        const int ch = 4 * Q + 2;
        const uint4 c = (ch < 16) ? cregs[ch] : sH4[(ch - 16) * NN + tid];
        d2 = dot8h(c, eh4[ch]);
    }
    {
        const int ch = 4 * Q + 3;
        const uint4 c = (ch < 16) ? cregs[ch] : sH4[(ch - 16) * NN + tid];
        d3 = dot8h(c, eh4[ch]);
    }
    acc = fmaf(-sp, (d0 + d1) + (d2 + d3), acc);
}

// warp-local 32x32 unit-lower solve: e_new = Minv * acc; publish scaled; reinit acc
__device__ __forceinline__ void solve32(float& acc, float& normv,
        const float* __restrict__ Mrow, __half* __restrict__ eh,
        float inv_sp, int tid)
{
    const float r = acc;
    float e0 = 0.f, e1 = 0.f, e2 = 0.f, e3 = 0.f;
#pragma unroll
    for (int k = 0; k < 32; k += 4) {
        e0 = fmaf(Mrow[k+0], __shfl_sync(0xffffffffu, r, k+0), e0);
        e1 = fmaf(Mrow[k+1], __shfl_sync(0xffffffffu, r, k+1), e1);
        e2 = fmaf(Mrow[k+2], __shfl_sync(0xffffffffu, r, k+2), e2);
        e3 = fmaf(Mrow[k+3], __shfl_sync(0xffffffffu, r, k+3), e3);
    }
    const float en = (e0 + e1) + (e2 + e3);
    eh[tid] = __float2half(en * inv_sp);   // publish e-hat
    acc = (1.0f - OMEGA) * en;             // start next iteration's accumulator
    normv = en * en;
}

__device__ __forceinline__ void norm_pub(float normv, float* __restrict__ wred,
                                         int bank, int wid, int lane)
{
    float v = normv;
#pragma unroll
    for (int o = 16; o; o >>= 1) v += __shfl_xor_sync(0xffffffffu, v, o);
    if (lane == 0) wred[bank * 8 + wid] = v;
}

__global__ void __launch_bounds__(NN, 2) sor_fused(
    const float* __restrict__ A, const float* __restrict__ xs,
    const float* __restrict__ theta, const float* __restrict__ rtol,
    float* __restrict__ out)
{
    extern __shared__ float sm[];
    __half*      eh   = (__half*)(sm + SM_EH);
    const uint4* eh4  = (const uint4*)(sm + SM_EH);
    float*       wred = sm + SM_WRED;
    float*       wred2= sm + SM_WRED2;
    uint4*       sH4  = (uint4*)(sm + SM_MAT);
    float*       scr  = sm + SM_SCR;

    const int b = blockIdx.x, tid = threadIdx.x;
    const int wid = tid >> 5, lane = tid & 31;
    const size_t obase = (size_t)b * (MAXITER + 1);

    // -------- load row tid, scale by omega/a_ii, stage fp32 diag block, zero own
    //          lower (j<=tid), convert to half2, split regs/smem ----------------
    const float*  Ar  = A + ((size_t)b * NN + tid) * NN;
    const float4* Ar4 = (const float4*)Ar;
    const float sc = OMEGA / Ar[tid];
    float* myscr = scr + wid * 1056;
    uint4 cregs[16];
#pragma unroll
    for (int ch = 0; ch < 32; ++ch) {        // chunk = 8 cols
        float4 u = Ar4[2*ch+0], v = Ar4[2*ch+1];
        u.x *= sc; u.y *= sc; u.z *= sc; u.w *= sc;
        v.x *= sc; v.y *= sc; v.z *= sc; v.w *= sc;
        if ((ch >> 2) == wid) {              // chunk inside own 32-col block
            float cols[8] = {u.x,u.y,u.z,u.w,v.x,v.y,v.z,v.w};
            const int base = (ch & 3) * 8;
#pragma unroll
            for (int k = 0; k < 8; ++k) myscr[lane*33 + base + k] = cols[k];
#pragma unroll
            for (int k = 0; k < 8; ++k) if (8*ch + k <= tid) cols[k] = 0.f;
            u.x=cols[0]; u.y=cols[1]; u.z=cols[2]; u.w=cols[3];
            v.x=cols[4]; v.y=cols[5]; v.z=cols[6]; v.w=cols[7];
        }
        uint4 h;
        h.x = h2u(__floats2half2_rn(u.x, u.y));
        h.y = h2u(__floats2half2_rn(u.z, u.w));
        h.z = h2u(__floats2half2_rn(v.x, v.y));
        h.w = h2u(__floats2half2_rn(v.z, v.w));
        if (ch < 16) cregs[ch] = h;
        else         sH4[(ch - 16) * NN + tid] = h;
    }

    // -------- e0 = xs - theta; warp-partial norms -------------------------------
    const float xv = xs[b * NN + tid];
    const float e0v = xv - theta[b * NN + tid];
    {
        float s1 = e0v * e0v, s2 = xv * xv;
#pragma unroll
        for (int o = 16; o; o >>= 1) {
            s1 += __shfl_xor_sync(0xffffffffu, s1, o);
            s2 += __shfl_xor_sync(0xffffffffu, s2, o);
        }
        if (lane == 0) { wred[wid] = s1; wred2[wid] = s2; }
    }

    // -------- per-warp 32x32 unit-lower inverse in scr --------------------------
    __syncwarp();
    {
        float mcol[32];
#pragma unroll
        for (int r = 0; r < 32; ++r) mcol[r] = (r == lane) ? 1.f : 0.f;
#pragma unroll
        for (int r = 1; r < 32; ++r) {
            float s = 0.f;
#pragma unroll
            for (int j = 0; j < r; ++j) s = fmaf(myscr[r * 33 + j], mcol[j], s);
            mcol[r] -= s;
        }
        __syncwarp();
#pragma unroll
        for (int r = 0; r < 32; ++r) myscr[r * 33 + lane] = mcol[r];
    }
    __syncwarp();
    float Mrow[32];
#pragma unroll
    for (int c = 0; c < 32; ++c) Mrow[c] = myscr[lane * 33 + c];

    __syncthreads();   // wred/wred2 + sH4 visible

    // -------- err0 / xtol (identical in every thread); publish e-hat ------------
    float sp_cur, xtol, inv_sp;
    {
        float a1 = 0.f, a2 = 0.f;
#pragma unroll
        for (int w = 0; w < 8; ++w) { a1 += wred[w]; a2 += wred2[w]; }
        sp_cur = sqrtf(a1);                 // err0
        xtol   = sqrtf(a2) * rtol[b];
        inv_sp = 1.0f / sp_cur;
        if (tid == 0) out[obase] = sp_cur;
    }
    eh[tid] = __float2half(e0v * inv_sp);
    __syncthreads();   // e-hat visible

    // -------- prologue: warp p consumes blocks p..7 of e0 (scale err0) ----------
    float acc = (1.0f - OMEGA) * e0v;
    if (wid == 0) consume32<0>(acc, sp_cur, cregs, sH4, eh4, tid);
    if (wid <= 1) consume32<1>(acc, sp_cur, cregs, sH4, eh4, tid);
    if (wid <= 2) consume32<2>(acc, sp_cur, cregs, sH4, eh4, tid);
    if (wid <= 3) consume32<3>(acc, sp_cur, cregs, sH4, eh4, tid);
    if (wid <= 4) consume32<4>(acc, sp_cur, cregs, sH4, eh4, tid);
    if (wid <= 5) consume32<5>(acc, sp_cur, cregs, sH4, eh4, tid);
    if (wid <= 6) consume32<6>(acc, sp_cur, cregs, sH4, eh4, tid);
    consume32<7>(acc, sp_cur, cregs, sH4, eh4, tid);

    // -------- pipelined mainloop: 8 warp-local stages ---------------------------
    float normv = 0.f;
    int t = 1;
    for (; t <= MAXITER; ++t) {
        // ===== stage 0 =====
        __syncthreads();                    // block 7 of iter t-1 published
        const float sp_old = sp_cur;
        if (t > 1) {
            float s = 0.f;
#pragma unroll
            for (int w = 0; w < 8; ++w) s += wred[((t - 1) & 1) * 8 + w];
            const float err = sqrtf(s);
            if (tid == 0) out[obase + (t - 1)] = err;
            sp_cur = err; inv_sp = 1.0f / err;
        }
        if (sp_cur <= xtol) break;
        if (t > 1) consume32<7>(acc, sp_old, cregs, sH4, eh4, tid);
        if (wid == 0) solve32(acc, normv, Mrow, eh, inv_sp, tid);

#define STAGE(S)                                                        \
        __syncthreads();                                                \
        consume32<S-1>(acc, sp_cur, cregs, sH4, eh4, tid);              \
        if (wid == S-1) norm_pub(normv, wred, t & 1, wid, lane);        \
        if (wid == S)   solve32(acc, normv, Mrow, eh, inv_sp, tid);

        STAGE(1) STAGE(2) STAGE(3) STAGE(4) STAGE(5) STAGE(6) STAGE(7)
#undef STAGE
        if (wid == 7) norm_pub(normv, wred, t & 1, wid, lane);
    }

    // -------- epilogue -----------------------------------------------------------
    int zf;
    if (t > MAXITER) {                      // natural exit: err_MAXITER unwritten
        __syncthreads();
        float s = 0.f;
#pragma unroll
        for (int w = 0; w < 8; ++w) s += wred[((MAXITER) & 1) * 8 + w];
        if (tid == 0) out[obase + MAXITER] = sqrtf(s);
        zf = MAXITER + 1;
    } else {
        zf = t;                             // broke at pass t: zero t..MAXITER
    }
    for (int z = zf + tid; z <= MAXITER; z += NN)
        out[obase + z] = 0.f;
}

// ---------------------------------------------------------------------------
extern "C" void kernel_launch(void* const* d_in, const int* in_sizes, int n_in,
                              void* d_out, int out_size) {
    const float* A     = (const float*)d_in[0];
    // d_in[1] = b — not needed (error-vector formulation)
    const float* xs    = (const float*)d_in[2];
    const float* theta = (const float*)d_in[3];
    const float* rtol  = (const float*)d_in[4];
    float* out = (float*)d_out;

    static int smem_set = 0;
    if (!smem_set) {
        cudaFuncSetAttribute(sor_fused, cudaFuncAttributeMaxDynamicSharedMemorySize,
                             SMEM_FLOATS * (int)sizeof(float));
        smem_set = 1;
    }
    sor_fused<<<BS, NN, SMEM_FLOATS * sizeof(float)>>>(A, xs, theta, rtol, out);
}